// round 10
// baseline (speedup 1.0000x reference)
#include <cuda_runtime.h>
#include <cuda_bf16.h>
#include <math.h>

#define B_  2
#define T_  2048
#define C_  1024
#define H_  16
#define D_  64
#define M_  (B_ * T_)     // 4096 rows
#define N3  (3 * C_)      // fused QKV width

// K-dim permutation (within each 8-group): pos(c) = 2*(c&3) + ((c>>2)&1).
// Applied identically to both GEMM operands along K -> product bit-identical,
// but makes mma fragment pairs (qd, qd+4) ADJACENT -> LDS.64.

// ---------------- scratch (device globals: no allocation allowed) ----------
__device__ __align__(128) float g_qkv[(size_t)M_ * N3];    // fused q|k|v
__device__ __align__(128) float g_o[(size_t)M_ * C_];      // K-permuted cols
__device__ __align__(128) float g_xc[(size_t)M_ * C_];     // tf32 + K-perm
__device__ __align__(128) float g_wc[4][(size_t)C_ * C_];  // tf32 + K-perm
__device__ __align__(128) float2 g_rope_tab[T_ * 32];

// ---------------- helpers ----------------------------------------------------
__device__ __forceinline__ void cp16(void* smem_dst, const void* gmem_src) {
    unsigned s = (unsigned)__cvta_generic_to_shared(smem_dst);
    asm volatile("cp.async.cg.shared.global [%0], [%1], 16;\n"
                 :: "r"(s), "l"(gmem_src));
}
#define CP_COMMIT()  asm volatile("cp.async.commit_group;\n")
#define CP_WAIT(n)   asm volatile("cp.async.wait_group %0;\n" :: "n"(n))

__device__ __forceinline__ float tf32r(float f) {
    unsigned u;
    asm("cvt.rna.tf32.f32 %0, %1;" : "=r"(u) : "f"(f));
    return __uint_as_float(u);
}
__device__ __forceinline__ void mma8(float* d, const unsigned* a,
                                     const unsigned* b) {
    asm volatile(
        "mma.sync.aligned.m16n8k8.row.col.f32.tf32.tf32.f32 "
        "{%0,%1,%2,%3}, {%4,%5,%6,%7}, {%8,%9}, {%0,%1,%2,%3};"
        : "+f"(d[0]), "+f"(d[1]), "+f"(d[2]), "+f"(d[3])
        : "r"(a[0]), "r"(a[1]), "r"(a[2]), "r"(a[3]),
          "r"(b[0]), "r"(b[1]));
}

// ---------------------------------------------------------------------------
// combined tf32 pre-round + K-permute pass (all matrices have 1024 cols)
// ---------------------------------------------------------------------------
#define XN4 (M_ * C_ / 4)
#define WN4 (C_ * C_ / 4)

__global__ __launch_bounds__(256) void round_all_kernel(
    const float* __restrict__ x,
    const float* __restrict__ Wq, const float* __restrict__ Wk,
    const float* __restrict__ Wv, const float* __restrict__ Wo,
    float* __restrict__ xc, float* __restrict__ wc)
{
    int i = blockIdx.x * blockDim.x + threadIdx.x;
    const float* src;
    float* dst;
    int idx;
    if (i < XN4) {
        src = x; dst = xc; idx = i;
    } else {
        int r = i - XN4;
        int which = r / WN4;
        idx = r - which * WN4;
        const float* ws[4] = {Wq, Wk, Wv, Wo};
        src = ws[which];
        dst = wc + (size_t)which * (C_ * C_);
    }
    float4 t = ((const float4*)src)[idx];
    const int row = idx >> 8;             // 256 float4 per 1024-col row
    const int c0  = (idx & 255) << 2;
    float v[4] = {tf32r(t.x), tf32r(t.y), tf32r(t.z), tf32r(t.w)};
#pragma unroll
    for (int j = 0; j < 4; j++) {
        int c = c0 + j;
        int pos = (c & ~7) | ((c & 3) << 1) | ((c >> 2) & 1);
        dst[(size_t)row * 1024 + pos] = v[j];
    }
}

__global__ __launch_bounds__(256) void rope_table_kernel(float2* __restrict__ tab)
{
    int idx = blockIdx.x * blockDim.x + threadIdx.x;
    if (idx >= T_ * 32) return;
    int t = idx >> 5;
    int j = idx & 31;
    double inv = exp(-((double)(2 * j) / 64.0) * log(10000.0));
    double ang = (double)t * inv;
    tab[idx] = make_float2((float)cos(ang), (float)sin(ang));
}

// ---------------------------------------------------------------------------
// GEMM: Y[M,N] = A[M,K] @ B[N,K]^T, raw mma.sync m16n8k8 tf32.
// Operands K-PERMUTED -> fragment pairs adjacent -> LDS.64 (half the loads).
// XOR-swizzled smem (pair ^ 4*(row&3)), unpadded 32-float rows: conflict-free
// stores AND loads. 128x128 CTA tile, 4 warps, BK=32, 3-stage cp.async,
// one barrier per iter, 2 CTAs/SM.
// ---------------------------------------------------------------------------
template <bool ROPE>
__global__ __launch_bounds__(128, 2) void gemm_tn(
    const float* __restrict__ A, const float* __restrict__ Bm,
    float* __restrict__ Y, const float2* __restrict__ tab,
    int M, int N, int K)
{
    extern __shared__ float sg[];
    float* As = sg;                    // 3 x 128 x 32
    float* Bs = sg + 3 * 128 * 32;     // 3 x 128 x 32

    const int m0  = blockIdx.y * 128;
    const int n0  = blockIdx.x * 128;
    const int tid = threadIdx.x;
    const int w   = tid >> 5;
    const int wm  = w >> 1;
    const int wn  = w & 1;
    const int l   = tid & 31;
    const int g   = l >> 2;
    const int qd  = l & 3;
    const int sw  = l & 12;            // ((g&3)<<2) swizzle term

    float acc[4][8][4];
#pragma unroll
    for (int i = 0; i < 4; i++)
#pragma unroll
        for (int j = 0; j < 8; j++)
#pragma unroll
            for (int e = 0; e < 4; e++) acc[i][j][e] = 0.0f;

    auto load_stage = [&](int buf, int kc) {
#pragma unroll
        for (int i = tid; i < 1024; i += 128) {
            int r = i >> 3;
            int c = i & 7;
            int d = (((2 * c) ^ ((r & 3) << 2)) << 1);   // float offset in row
            cp16(&As[buf * 4096 + r * 32 + d],
                 &A[(size_t)(m0 + r) * K + kc + 4 * c]);
            cp16(&Bs[buf * 4096 + r * 32 + d],
                 &Bm[(size_t)(n0 + r) * K + kc + 4 * c]);
        }
    };

    load_stage(0, 0);
    CP_COMMIT();
    load_stage(1, 32);
    CP_COMMIT();

    const int NIT = K / 32;
    for (int it = 0; it < NIT; it++) {
        if (it < NIT - 1) { CP_WAIT(1); } else { CP_WAIT(0); }
        __syncthreads();
        if (it + 2 < NIT) {
            load_stage((it + 2) % 3, (it + 2) * 32);
            CP_COMMIT();
        }

        const float* Ab = &As[(it % 3) * 4096 + (wm * 64) * 32];
        const float* Bb = &Bs[(it % 3) * 4096 + (wn * 64) * 32];

#pragma unroll
        for (int k8 = 0; k8 < 4; k8++) {
            const int ko = ((((k8 << 2) | qd) ^ sw) << 1);
            unsigned av[4][4];
#pragma unroll
            for (int i = 0; i < 4; i++) {
                float2 va = *(const float2*)&Ab[(i * 16 + g)     * 32 + ko];
                float2 vc = *(const float2*)&Ab[(i * 16 + g + 8) * 32 + ko];
                av[i][0] = __float_as_uint(va.x);
                av[i][1] = __float_as_uint(vc.x);
                av[i][2] = __float_as_uint(va.y);
                av[i][3] = __float_as_uint(vc.y);
            }
            unsigned bv[8][2];
#pragma unroll
            for (int j = 0; j < 8; j++) {
                float2 vb = *(const float2*)&Bb[(j * 8 + g) * 32 + ko];
                bv[j][0] = __float_as_uint(vb.x);
                bv[j][1] = __float_as_uint(vb.y);
            }
#pragma unroll
            for (int i = 0; i < 4; i++)
#pragma unroll
                for (int j = 0; j < 8; j++)
                    mma8(acc[i][j], av[i], bv[j]);
        }
    }

    // epilogue (RoPE fused for q/k columns when ROPE=true); N-dim unpermuted
#pragma unroll
    for (int i = 0; i < 4; i++) {
        const int rA = m0 + wm * 64 + i * 16 + g;
        const int rB = rA + 8;
        const size_t rowA = (size_t)rA * N;
        const size_t rowB = (size_t)rB * N;
        const int tA = rA & (T_ - 1);
        const int tB = rB & (T_ - 1);
#pragma unroll
        for (int j = 0; j < 8; j++) {
            const int col = n0 + wn * 64 + j * 8 + 2 * qd;
            float e0 = acc[i][j][0], o0 = acc[i][j][1];
            float e1 = acc[i][j][2], o1 = acc[i][j][3];
            if (ROPE) {
                if (col < 2 * C_) {
                    const int jj = (col & (D_ - 1)) >> 1;
                    float2 csA = tab[tA * 32 + jj];
                    float2 csB = tab[tB * 32 + jj];
                    float ne0 = e0 * csA.x - o0 * csA.y;
                    float no0 = e0 * csA.y + o0 * csA.x;
                    float ne1 = e1 * csB.x - o1 * csB.y;
                    float no1 = e1 * csB.y + o1 * csB.x;
                    e0 = ne0; o0 = no0; e1 = ne1; o1 = no1;
                }
                e0 = tf32r(e0); o0 = tf32r(o0);
                e1 = tf32r(e1); o1 = tf32r(o1);
            }
            *(float2*)&Y[rowA + col] = make_float2(e0, o0);
            *(float2*)&Y[rowB + col] = make_float2(e1, o1);
        }
    }
}

// ---------------------------------------------------------------------------
// Flash attention (causal), FA-2 style, fused-qkv input (row stride N3).
// BM=64 (4 warps x 16 rows), BN=64, D=64, mma.sync m16n8k8 tf32.
// Output columns stored K-PERMUTED so the Wo GEMM can vector-load fragments.
// ---------------------------------------------------------------------------
#define FST 68
#define VST 72

__global__ __launch_bounds__(128, 2) void flash_kernel(
    const float* __restrict__ qkv, float* __restrict__ o)
{
    extern __shared__ float sm[];
    float* QP = sm;                     // 64*FST: Q staging, then P strips
    float* Kb = QP + 64 * FST;          // 2 x 64*FST
    float* Vb = Kb + 128 * FST;         // 2 x 64*VST

    const int bh  = blockIdx.y;
    const int b   = bh >> 4;
    const int h   = bh & 15;
    const int q0  = (gridDim.x - 1 - blockIdx.x) * 64;
    const int tid = threadIdx.x;
    const int w   = tid >> 5;
    const int l   = tid & 31;
    const int g   = l >> 2;
    const int qd  = l & 3;
    const float scale = 0.125f;

    const size_t qbase = (size_t)(b * T_ + q0) * N3 + h * D_;
    const size_t orow  = (size_t)(b * T_ + q0) * C_ + h * D_;

    auto kv_load = [&](int buf, int n0) {
        const size_t kbase = (size_t)(b * T_ + n0) * N3 + h * D_ + C_;
#pragma unroll
        for (int i = tid; i < 1024; i += 128) {
            int r = i >> 4, c = (i & 15) << 2;
            cp16(&Kb[buf * 64 * FST + r * FST + c],
                 &qkv[kbase + (size_t)r * N3 + c]);
            cp16(&Vb[buf * 64 * VST + r * VST + c],
                 &qkv[kbase + (size_t)r * N3 + C_ + c]);
        }
    };

    kv_load(0, 0);
    CP_COMMIT();

    for (int i = tid; i < 1024; i += 128) {
        int r = i >> 4, c = (i & 15) << 2;
        float4 t4 = *(const float4*)&qkv[qbase + (size_t)r * N3 + c];
        t4.x *= scale; t4.y *= scale; t4.z *= scale; t4.w *= scale;
        *(float4*)&QP[r * FST + c] = t4;
    }
    __syncthreads();

    unsigned aq[8][4];
    float* Pw = QP + w * 16 * FST;
#pragma unroll
    for (int kt = 0; kt < 8; kt++) {
        aq[kt][0] = __float_as_uint(Pw[g * FST + kt * 8 + qd]);
        aq[kt][1] = __float_as_uint(Pw[(g + 8) * FST + kt * 8 + qd]);
        aq[kt][2] = __float_as_uint(Pw[g * FST + kt * 8 + qd + 4]);
        aq[kt][3] = __float_as_uint(Pw[(g + 8) * FST + kt * 8 + qd + 4]);
    }
    __syncwarp();

    float oacc[8][4];
#pragma unroll
    for (int nt = 0; nt < 8; nt++)
#pragma unroll
        for (int j = 0; j < 4; j++) oacc[nt][j] = 0.0f;
    float mA = -INFINITY, mB = -INFINITY, lA = 0.0f, lB = 0.0f;

    const int rA_loc = w * 16 + g;
    const int rB_loc = rA_loc + 8;

    for (int n0 = 0; n0 <= q0; n0 += 64) {
        const int buf = (n0 >> 6) & 1;
        CP_WAIT(0);
        __syncthreads();
        if (n0 + 64 <= q0) {
            kv_load(buf ^ 1, n0 + 64);
            CP_COMMIT();
        }

        const float* Ks = &Kb[buf * 64 * FST];
        const float* Vs = &Vb[buf * 64 * VST];

        float s[8][4];
#pragma unroll
        for (int nt = 0; nt < 8; nt++)
#pragma unroll
            for (int j = 0; j < 4; j++) s[nt][j] = 0.0f;

#pragma unroll
        for (int kt = 0; kt < 8; kt++) {
            unsigned bb[8][2];
#pragma unroll
            for (int nt = 0; nt < 8; nt++) {
                bb[nt][0] = __float_as_uint(Ks[(nt * 8 + g) * FST + kt * 8 + qd]);
                bb[nt][1] = __float_as_uint(Ks[(nt * 8 + g) * FST + kt * 8 + qd + 4]);
            }
#pragma unroll
            for (int nt = 0; nt < 8; nt++)
                mma8(s[nt], aq[kt], bb[nt]);
        }

        if (n0 == q0) {
#pragma unroll
            for (int nt = 0; nt < 8; nt++) {
                int c0 = nt * 8 + 2 * qd;
                if (c0     > rA_loc) s[nt][0] = -INFINITY;
                if (c0 + 1 > rA_loc) s[nt][1] = -INFINITY;
                if (c0     > rB_loc) s[nt][2] = -INFINITY;
                if (c0 + 1 > rB_loc) s[nt][3] = -INFINITY;
            }
        }

        float mxA = -INFINITY, mxB = -INFINITY;
#pragma unroll
        for (int nt = 0; nt < 8; nt++) {
            mxA = fmaxf(mxA, fmaxf(s[nt][0], s[nt][1]));
            mxB = fmaxf(mxB, fmaxf(s[nt][2], s[nt][3]));
        }
        mxA = fmaxf(mxA, __shfl_xor_sync(0xffffffffu, mxA, 1));
        mxA = fmaxf(mxA, __shfl_xor_sync(0xffffffffu, mxA, 2));
        mxB = fmaxf(mxB, __shfl_xor_sync(0xffffffffu, mxB, 1));
        mxB = fmaxf(mxB, __shfl_xor_sync(0xffffffffu, mxB, 2));

        float nmA = fmaxf(mA, mxA);
        float nmB = fmaxf(mB, mxB);
        float alA = __expf(mA - nmA);
        float alB = __expf(mB - nmB);
        mA = nmA; mB = nmB;

        float sumA = 0.0f, sumB = 0.0f;
#pragma unroll
        for (int nt = 0; nt < 8; nt++) {
            float p0 = __expf(s[nt][0] - nmA);
            float p1 = __expf(s[nt][1] - nmA);
            float p2 = __expf(s[nt][2] - nmB);
            float p3 = __expf(s[nt][3] - nmB);
            s[nt][0] = p0; s[nt][1] = p1; s[nt][2] = p2; s[nt][3] = p3;
            sumA += p0 + p1;
            sumB += p2 + p3;
        }
        sumA += __shfl_xor_sync(0xffffffffu, sumA, 1);
        sumA += __shfl_xor_sync(0xffffffffu, sumA, 2);
        sumB += __shfl_xor_sync(0xffffffffu, sumB, 1);
        sumB += __shfl_xor_sync(0xffffffffu, sumB, 2);
        lA = lA * alA + sumA;
        lB = lB * alB + sumB;

#pragma unroll
        for (int nt = 0; nt < 8; nt++) {
            oacc[nt][0] *= alA; oacc[nt][1] *= alA;
            oacc[nt][2] *= alB; oacc[nt][3] *= alB;
        }

#pragma unroll
        for (int nt = 0; nt < 8; nt++) {
            *(float2*)&Pw[g * FST + nt * 8 + 2 * qd] =
                make_float2(tf32r(s[nt][0]), tf32r(s[nt][1]));
            *(float2*)&Pw[(g + 8) * FST + nt * 8 + 2 * qd] =
                make_float2(tf32r(s[nt][2]), tf32r(s[nt][3]));
        }
        __syncwarp();

#pragma unroll
        for (int kt = 0; kt < 8; kt++) {
            unsigned ap[4];
            ap[0] = __float_as_uint(Pw[g * FST + kt * 8 + qd]);
            ap[1] = __float_as_uint(Pw[(g + 8) * FST + kt * 8 + qd]);
            ap[2] = __float_as_uint(Pw[g * FST + kt * 8 + qd + 4]);
            ap[3] = __float_as_uint(Pw[(g + 8) * FST + kt * 8 + qd + 4]);
#pragma unroll
            for (int nt = 0; nt < 8; nt++) {
                unsigned bb[2];
                bb[0] = __float_as_uint(Vs[(kt * 8 + qd) * VST + nt * 8 + g]);
                bb[1] = __float_as_uint(Vs[(kt * 8 + qd + 4) * VST + nt * 8 + g]);
                mma8(oacc[nt], ap, bb);
            }
        }
    }

    // normalize + write, K-PERMUTED columns (pos(2qd), pos(2qd)+2)
    const float rAi = 1.0f / lA;
    const float rBi = 1.0f / lB;
    const int cw  = 2 * qd;
    const int pos = ((cw & 3) << 1) | ((cw >> 2) & 1);
#pragma unroll
    for (int nt = 0; nt < 8; nt++) {
        int col0 = nt * 8 + pos;
        o[orow + (size_t)rA_loc * C_ + col0]     = tf32r(oacc[nt][0] * rAi);
        o[orow + (size_t)rA_loc * C_ + col0 + 2] = tf32r(oacc[nt][1] * rAi);
        o[orow + (size_t)rB_loc * C_ + col0]     = tf32r(oacc[nt][2] * rBi);
        o[orow + (size_t)rB_loc * C_ + col0 + 2] = tf32r(oacc[nt][3] * rBi);
    }
}

// ---------------------------------------------------------------------------
extern "C" void kernel_launch(void* const* d_in, const int* in_sizes, int n_in,
                              void* d_out, int out_size)
{
    (void)in_sizes; (void)n_in; (void)out_size;
    const float* x  = (const float*)d_in[0];
    const float* Wq = (const float*)d_in[1];
    const float* Wk = (const float*)d_in[2];
    const float* Wv = (const float*)d_in[3];
    const float* Wo = (const float*)d_in[4];
    float* out = (float*)d_out;

    float *qkv, *ob, *xc, *wc;
    float2* tab;
    cudaGetSymbolAddress((void**)&qkv, g_qkv);
    cudaGetSymbolAddress((void**)&ob,  g_o);
    cudaGetSymbolAddress((void**)&xc,  g_xc);
    cudaGetSymbolAddress((void**)&wc,  g_wc);
    cudaGetSymbolAddress((void**)&tab, g_rope_tab);

    float* wqkv = wc;                          // [3C][C], contiguous
    float* woc  = wc + 3 * (size_t)C_ * C_;

    const int totn4 = XN4 + 4 * WN4;
    round_all_kernel<<<(totn4 + 255) / 256, 256>>>(x, Wq, Wk, Wv, Wo, xc, wc);
    rope_table_kernel<<<(T_ * 32 + 255) / 256, 256>>>(tab);

    const int gsmem = 6 * 128 * 32 * (int)sizeof(float);   // 98,304 B
    cudaFuncSetAttribute(gemm_tn<true>,
                         cudaFuncAttributeMaxDynamicSharedMemorySize, gsmem);
    cudaFuncSetAttribute(gemm_tn<false>,
                         cudaFuncAttributeMaxDynamicSharedMemorySize, gsmem);

    // fused QKV projection + RoPE epilogue
    gemm_tn<true><<<dim3(N3 / 128, M_ / 128), 128, gsmem>>>(
        xc, wqkv, qkv, tab, M_, N3, C_);

    const int fsmem = (64 * FST + 128 * FST + 128 * VST) * (int)sizeof(float);
    cudaFuncSetAttribute(flash_kernel,
                         cudaFuncAttributeMaxDynamicSharedMemorySize, fsmem);
    flash_kernel<<<dim3(T_ / 64, B_ * H_), 128, fsmem>>>(qkv, ob);

    gemm_tn<false><<<dim3(C_ / 128, M_ / 128), 128, gsmem>>>(
        ob, woc, out, tab, M_, C_, C_);
}

// round 11
// speedup vs baseline: 1.5291x; 1.5291x over previous
#include <cuda_runtime.h>
#include <cuda_bf16.h>
#include <math.h>

#define B_  2
#define T_  2048
#define C_  1024
#define H_  16
#define D_  64
#define M_  (B_ * T_)     // 4096 rows
#define N3  (3 * C_)      // fused QKV width

// K-dim permutation within 8-groups: pos(c) = 2*(c&3) + ((c>>2)&1).
// Applied identically to x and Wqkv along K (contraction dim) -> QKV product
// bit-identical, but mma fragment pairs (qd, qd+4) become ADJACENT -> LDS.64.
// Out-of-group order: out = [v0, v4, v1, v5, v2, v6, v3, v7].

// ---------------- scratch (device globals: no allocation allowed) ----------
__device__ __align__(128) float g_qkv[(size_t)M_ * N3];    // fused q|k|v
__device__ __align__(128) float g_o[(size_t)M_ * C_];
__device__ __align__(128) float g_xc[(size_t)M_ * C_];     // tf32 + K-perm
__device__ __align__(128) float g_wc[4][(size_t)C_ * C_];  // Wq|Wk|Wv perm, Wo plain
__device__ __align__(128) float2 g_rope_tab[T_ * 32];

// ---------------- helpers ----------------------------------------------------
__device__ __forceinline__ void cp16(void* smem_dst, const void* gmem_src) {
    unsigned s = (unsigned)__cvta_generic_to_shared(smem_dst);
    asm volatile("cp.async.cg.shared.global [%0], [%1], 16;\n"
                 :: "r"(s), "l"(gmem_src));
}
#define CP_COMMIT()  asm volatile("cp.async.commit_group;\n")
#define CP_WAIT(n)   asm volatile("cp.async.wait_group %0;\n" :: "n"(n))

__device__ __forceinline__ float tf32r(float f) {
    unsigned u;
    asm("cvt.rna.tf32.f32 %0, %1;" : "=r"(u) : "f"(f));
    return __uint_as_float(u);
}
__device__ __forceinline__ void mma8(float* d, const unsigned* a,
                                     const unsigned* b) {
    asm volatile(
        "mma.sync.aligned.m16n8k8.row.col.f32.tf32.tf32.f32 "
        "{%0,%1,%2,%3}, {%4,%5,%6,%7}, {%8,%9}, {%0,%1,%2,%3};"
        : "+f"(d[0]), "+f"(d[1]), "+f"(d[2]), "+f"(d[3])
        : "r"(a[0]), "r"(a[1]), "r"(a[2]), "r"(a[3]),
          "r"(b[0]), "r"(b[1]));
}

// ---------------------------------------------------------------------------
// combined tf32 pre-round pass, one 8-float group per thread.
// x, Wq, Wk, Wv: permuted in registers (vector LDG + vector STG, no scatter).
// Wo: plain round.
// ---------------------------------------------------------------------------
#define XN8 (M_ * C_ / 8)
#define WN8 (C_ * C_ / 8)

__global__ __launch_bounds__(256) void round_all_kernel(
    const float* __restrict__ x,
    const float* __restrict__ Wq, const float* __restrict__ Wk,
    const float* __restrict__ Wv, const float* __restrict__ Wo,
    float* __restrict__ xc, float* __restrict__ wc)
{
    int i = blockIdx.x * blockDim.x + threadIdx.x;
    if (i >= XN8 + 4 * WN8) return;
    const float* src;
    float* dst;
    int idx;
    bool perm = true;
    if (i < XN8) {
        src = x; dst = xc; idx = i;
    } else {
        int r = i - XN8;
        int which = r / WN8;
        idx = r - which * WN8;
        const float* ws[4] = {Wq, Wk, Wv, Wo};
        src = ws[which];
        dst = wc + (size_t)which * (C_ * C_);
        perm = (which < 3);
    }
    float4 t0 = ((const float4*)src)[2 * idx];
    float4 t1 = ((const float4*)src)[2 * idx + 1];
    float v0 = tf32r(t0.x), v1 = tf32r(t0.y), v2 = tf32r(t0.z), v3 = tf32r(t0.w);
    float v4 = tf32r(t1.x), v5 = tf32r(t1.y), v6 = tf32r(t1.z), v7 = tf32r(t1.w);
    float4 o0, o1;
    if (perm) {
        o0 = make_float4(v0, v4, v1, v5);
        o1 = make_float4(v2, v6, v3, v7);
    } else {
        o0 = make_float4(v0, v1, v2, v3);
        o1 = make_float4(v4, v5, v6, v7);
    }
    ((float4*)dst)[2 * idx]     = o0;
    ((float4*)dst)[2 * idx + 1] = o1;
}

__global__ __launch_bounds__(256) void rope_table_kernel(float2* __restrict__ tab)
{
    int idx = blockIdx.x * blockDim.x + threadIdx.x;
    if (idx >= T_ * 32) return;
    int t = idx >> 5;
    int j = idx & 31;
    double inv = exp(-((double)(2 * j) / 64.0) * log(10000.0));
    double ang = (double)t * inv;
    tab[idx] = make_float2((float)cos(ang), (float)sin(ang));
}

// ---------------------------------------------------------------------------
// QKV GEMM: qkv[M,3C] = x @ [Wq;Wk;Wv]^T, K-permuted operands.
// ST=32 unpadded, XOR swizzle (row&3)<<3 at 8-float granularity:
// conflict-free cp.async stores AND LDS.64 fragment loads (verified per-phase).
// 128x128 tile, 4 warps, BK=32, 3-stage, one barrier/iter, 2 CTAs/SM.
// RoPE fused in the epilogue; output N-dim unpermuted (flash-compatible).
// ---------------------------------------------------------------------------
__global__ __launch_bounds__(128, 2) void gemm_qkv(
    const float* __restrict__ A, const float* __restrict__ Bm,
    float* __restrict__ Y, const float2* __restrict__ tab,
    int M, int N, int K)
{
    extern __shared__ float sg[];
    float* As = sg;                    // 3 x 128 x 32
    float* Bs = sg + 3 * 4096;         // 3 x 128 x 32

    const int m0  = blockIdx.y * 128;
    const int n0  = blockIdx.x * 128;
    const int tid = threadIdx.x;
    const int w   = tid >> 5;
    const int wm  = w >> 1;
    const int wn  = w & 1;
    const int l   = tid & 31;
    const int g   = l >> 2;
    const int qd  = l & 3;
    const int swz = (g & 3) << 3;      // XOR term, 8-float granularity

    float acc[4][8][4];
#pragma unroll
    for (int i = 0; i < 4; i++)
#pragma unroll
        for (int j = 0; j < 8; j++)
#pragma unroll
            for (int e = 0; e < 4; e++) acc[i][j][e] = 0.0f;

    auto load_stage = [&](int buf, int kc) {
#pragma unroll
        for (int i = tid; i < 1024; i += 128) {
            int r = i >> 3;
            int c = i & 7;
            int d = (4 * c) ^ ((r & 3) << 3);
            cp16(&As[buf * 4096 + r * 32 + d],
                 &A[(size_t)(m0 + r) * K + kc + 4 * c]);
            cp16(&Bs[buf * 4096 + r * 32 + d],
                 &Bm[(size_t)(n0 + r) * K + kc + 4 * c]);
        }
    };

    load_stage(0, 0);
    CP_COMMIT();
    load_stage(1, 32);
    CP_COMMIT();

    const int NIT = K / 32;
    for (int it = 0; it < NIT; it++) {
        if (it < NIT - 1) { CP_WAIT(1); } else { CP_WAIT(0); }
        __syncthreads();
        if (it + 2 < NIT) {
            load_stage((it + 2) % 3, (it + 2) * 32);
            CP_COMMIT();
        }

        const float* Ab = &As[(it % 3) * 4096 + (wm * 64) * 32];
        const float* Bb = &Bs[(it % 3) * 4096 + (wn * 64) * 32];

#pragma unroll
        for (int k8 = 0; k8 < 4; k8++) {
            const int ko = (8 * k8 + 2 * qd) ^ swz;
            unsigned av[4][4];
#pragma unroll
            for (int i = 0; i < 4; i++) {
                float2 va = *(const float2*)&Ab[(i * 16 + g)     * 32 + ko];
                float2 vc = *(const float2*)&Ab[(i * 16 + g + 8) * 32 + ko];
                av[i][0] = __float_as_uint(va.x);
                av[i][1] = __float_as_uint(vc.x);
                av[i][2] = __float_as_uint(va.y);
                av[i][3] = __float_as_uint(vc.y);
            }
            unsigned bv[8][2];
#pragma unroll
            for (int j = 0; j < 8; j++) {
                float2 vb = *(const float2*)&Bb[(j * 8 + g) * 32 + ko];
                bv[j][0] = __float_as_uint(vb.x);
                bv[j][1] = __float_as_uint(vb.y);
            }
#pragma unroll
            for (int i = 0; i < 4; i++)
#pragma unroll
                for (int j = 0; j < 8; j++)
                    mma8(acc[i][j], av[i], bv[j]);
        }
    }

    // epilogue: RoPE on q/k columns, tf32-round, float2 stores (unpermuted N)
#pragma unroll
    for (int i = 0; i < 4; i++) {
        const int rA = m0 + wm * 64 + i * 16 + g;
        const int rB = rA + 8;
        const size_t rowA = (size_t)rA * N;
        const size_t rowB = (size_t)rB * N;
        const int tA = rA & (T_ - 1);
        const int tB = rB & (T_ - 1);
#pragma unroll
        for (int j = 0; j < 8; j++) {
            const int col = n0 + wn * 64 + j * 8 + 2 * qd;
            float e0 = acc[i][j][0], o0 = acc[i][j][1];
            float e1 = acc[i][j][2], o1 = acc[i][j][3];
            if (col < 2 * C_) {
                const int jj = (col & (D_ - 1)) >> 1;
                float2 csA = tab[tA * 32 + jj];
                float2 csB = tab[tB * 32 + jj];
                float ne0 = e0 * csA.x - o0 * csA.y;
                float no0 = e0 * csA.y + o0 * csA.x;
                float ne1 = e1 * csB.x - o1 * csB.y;
                float no1 = e1 * csB.y + o1 * csB.x;
                e0 = ne0; o0 = no0; e1 = ne1; o1 = no1;
            }
            e0 = tf32r(e0); o0 = tf32r(o0);
            e1 = tf32r(e1); o1 = tf32r(o1);
            *(float2*)&Y[rowA + col] = make_float2(e0, o0);
            *(float2*)&Y[rowB + col] = make_float2(e1, o1);
        }
    }
}

// ---------------------------------------------------------------------------
// Wo GEMM: out[M,C] = ob @ Wo^T. Exact R9 kernel (unpermuted, GST=36,
// scalar fragment loads, 3-stage, one barrier/iter, 2 CTAs/SM).
// ---------------------------------------------------------------------------
#define GST 36

__global__ __launch_bounds__(128, 2) void gemm_wo(
    const float* __restrict__ A, const float* __restrict__ Bm,
    float* __restrict__ Y, int M, int N, int K)
{
    extern __shared__ float sg[];
    float* As = sg;                    // 3 x 128 x GST
    float* Bs = sg + 3 * 128 * GST;

    const int m0  = blockIdx.y * 128;
    const int n0  = blockIdx.x * 128;
    const int tid = threadIdx.x;
    const int w   = tid >> 5;
    const int wm  = w >> 1;
    const int wn  = w & 1;
    const int l   = tid & 31;
    const int g   = l >> 2;
    const int qd  = l & 3;

    float acc[4][8][4];
#pragma unroll
    for (int i = 0; i < 4; i++)
#pragma unroll
        for (int j = 0; j < 8; j++)
#pragma unroll
            for (int e = 0; e < 4; e++) acc[i][j][e] = 0.0f;

    auto load_stage = [&](int buf, int kc) {
#pragma unroll
        for (int i = tid; i < 1024; i += 128) {
            int r = i >> 3;
            int c = (i & 7) << 2;
            cp16(&As[buf * 128 * GST + r * GST + c],
                 &A[(size_t)(m0 + r) * K + kc + c]);
            cp16(&Bs[buf * 128 * GST + r * GST + c],
                 &Bm[(size_t)(n0 + r) * K + kc + c]);
        }
    };

    load_stage(0, 0);
    CP_COMMIT();
    load_stage(1, 32);
    CP_COMMIT();

    const int NIT = K / 32;
    for (int it = 0; it < NIT; it++) {
        if (it < NIT - 1) { CP_WAIT(1); } else { CP_WAIT(0); }
        __syncthreads();
        if (it + 2 < NIT) {
            load_stage((it + 2) % 3, (it + 2) * 32);
            CP_COMMIT();
        }

        const float* Ab = &As[(it % 3) * 128 * GST + (wm * 64) * GST];
        const float* Bb = &Bs[(it % 3) * 128 * GST + (wn * 64) * GST];

#pragma unroll
        for (int k8 = 0; k8 < 4; k8++) {
            unsigned av[4][4];
#pragma unroll
            for (int i = 0; i < 4; i++) {
                av[i][0] = __float_as_uint(Ab[(i * 16 + g)     * GST + k8 * 8 + qd]);
                av[i][1] = __float_as_uint(Ab[(i * 16 + g + 8) * GST + k8 * 8 + qd]);
                av[i][2] = __float_as_uint(Ab[(i * 16 + g)     * GST + k8 * 8 + qd + 4]);
                av[i][3] = __float_as_uint(Ab[(i * 16 + g + 8) * GST + k8 * 8 + qd + 4]);
            }
            unsigned bv[8][2];
#pragma unroll
            for (int j = 0; j < 8; j++) {
                bv[j][0] = __float_as_uint(Bb[(j * 8 + g) * GST + k8 * 8 + qd]);
                bv[j][1] = __float_as_uint(Bb[(j * 8 + g) * GST + k8 * 8 + qd + 4]);
            }
#pragma unroll
            for (int i = 0; i < 4; i++)
#pragma unroll
                for (int j = 0; j < 8; j++)
                    mma8(acc[i][j], av[i], bv[j]);
        }
    }

#pragma unroll
    for (int i = 0; i < 4; i++) {
        const size_t rowA = (size_t)(m0 + wm * 64 + i * 16 + g) * N;
        const size_t rowB = rowA + 8 * N;
#pragma unroll
        for (int j = 0; j < 8; j++) {
            const int col = n0 + wn * 64 + j * 8 + 2 * qd;
            *(float2*)&Y[rowA + col] = make_float2(acc[i][j][0], acc[i][j][1]);
            *(float2*)&Y[rowB + col] = make_float2(acc[i][j][2], acc[i][j][3]);
        }
    }
}

// ---------------------------------------------------------------------------
// Flash attention (causal), FA-2 style (exact R9 + PV V-fragment hoist).
// BM=64 (4 warps x 16 rows), BN=64, D=64, mma.sync m16n8k8 tf32.
// ---------------------------------------------------------------------------
#define FST 68
#define VST 72

__global__ __launch_bounds__(128, 2) void flash_kernel(
    const float* __restrict__ qkv, float* __restrict__ o)
{
    extern __shared__ float sm[];
    float* QP = sm;                     // 64*FST: Q staging, then P strips
    float* Kb = QP + 64 * FST;          // 2 x 64*FST
    float* Vb = Kb + 128 * FST;         // 2 x 64*VST

    const int bh  = blockIdx.y;
    const int b   = bh >> 4;
    const int h   = bh & 15;
    const int q0  = (gridDim.x - 1 - blockIdx.x) * 64;
    const int tid = threadIdx.x;
    const int w   = tid >> 5;
    const int l   = tid & 31;
    const int g   = l >> 2;
    const int qd  = l & 3;
    const float scale = 0.125f;

    const size_t qbase = (size_t)(b * T_ + q0) * N3 + h * D_;
    const size_t orow  = (size_t)(b * T_ + q0) * C_ + h * D_;

    auto kv_load = [&](int buf, int n0) {
        const size_t kbase = (size_t)(b * T_ + n0) * N3 + h * D_ + C_;
#pragma unroll
        for (int i = tid; i < 1024; i += 128) {
            int r = i >> 4, c = (i & 15) << 2;
            cp16(&Kb[buf * 64 * FST + r * FST + c],
                 &qkv[kbase + (size_t)r * N3 + c]);
            cp16(&Vb[buf * 64 * VST + r * VST + c],
                 &qkv[kbase + (size_t)r * N3 + C_ + c]);
        }
    };

    kv_load(0, 0);
    CP_COMMIT();

    for (int i = tid; i < 1024; i += 128) {
        int r = i >> 4, c = (i & 15) << 2;
        float4 t4 = *(const float4*)&qkv[qbase + (size_t)r * N3 + c];
        t4.x *= scale; t4.y *= scale; t4.z *= scale; t4.w *= scale;
        *(float4*)&QP[r * FST + c] = t4;
    }
    __syncthreads();

    unsigned aq[8][4];
    float* Pw = QP + w * 16 * FST;
#pragma unroll
    for (int kt = 0; kt < 8; kt++) {
        aq[kt][0] = __float_as_uint(Pw[g * FST + kt * 8 + qd]);
        aq[kt][1] = __float_as_uint(Pw[(g + 8) * FST + kt * 8 + qd]);
        aq[kt][2] = __float_as_uint(Pw[g * FST + kt * 8 + qd + 4]);
        aq[kt][3] = __float_as_uint(Pw[(g + 8) * FST + kt * 8 + qd + 4]);
    }
    __syncwarp();

    float oacc[8][4];
#pragma unroll
    for (int nt = 0; nt < 8; nt++)
#pragma unroll
        for (int j = 0; j < 4; j++) oacc[nt][j] = 0.0f;
    float mA = -INFINITY, mB = -INFINITY, lA = 0.0f, lB = 0.0f;

    const int rA_loc = w * 16 + g;
    const int rB_loc = rA_loc + 8;

    for (int n0 = 0; n0 <= q0; n0 += 64) {
        const int buf = (n0 >> 6) & 1;
        CP_WAIT(0);
        __syncthreads();
        if (n0 + 64 <= q0) {
            kv_load(buf ^ 1, n0 + 64);
            CP_COMMIT();
        }

        const float* Ks = &Kb[buf * 64 * FST];
        const float* Vs = &Vb[buf * 64 * VST];

        float s[8][4];
#pragma unroll
        for (int nt = 0; nt < 8; nt++)
#pragma unroll
            for (int j = 0; j < 4; j++) s[nt][j] = 0.0f;

#pragma unroll
        for (int kt = 0; kt < 8; kt++) {
            unsigned bb[8][2];
#pragma unroll
            for (int nt = 0; nt < 8; nt++) {
                bb[nt][0] = __float_as_uint(Ks[(nt * 8 + g) * FST + kt * 8 + qd]);
                bb[nt][1] = __float_as_uint(Ks[(nt * 8 + g) * FST + kt * 8 + qd + 4]);
            }
#pragma unroll
            for (int nt = 0; nt < 8; nt++)
                mma8(s[nt], aq[kt], bb[nt]);
        }

        if (n0 == q0) {
#pragma unroll
            for (int nt = 0; nt < 8; nt++) {
                int c0 = nt * 8 + 2 * qd;
                if (c0     > rA_loc) s[nt][0] = -INFINITY;
                if (c0 + 1 > rA_loc) s[nt][1] = -INFINITY;
                if (c0     > rB_loc) s[nt][2] = -INFINITY;
                if (c0 + 1 > rB_loc) s[nt][3] = -INFINITY;
            }
        }

        float mxA = -INFINITY, mxB = -INFINITY;
#pragma unroll
        for (int nt = 0; nt < 8; nt++) {
            mxA = fmaxf(mxA, fmaxf(s[nt][0], s[nt][1]));
            mxB = fmaxf(mxB, fmaxf(s[nt][2], s[nt][3]));
        }
        mxA = fmaxf(mxA, __shfl_xor_sync(0xffffffffu, mxA, 1));
        mxA = fmaxf(mxA, __shfl_xor_sync(0xffffffffu, mxA, 2));
        mxB = fmaxf(mxB, __shfl_xor_sync(0xffffffffu, mxB, 1));
        mxB = fmaxf(mxB, __shfl_xor_sync(0xffffffffu, mxB, 2));

        float nmA = fmaxf(mA, mxA);
        float nmB = fmaxf(mB, mxB);
        float alA = __expf(mA - nmA);
        float alB = __expf(mB - nmB);
        mA = nmA; mB = nmB;

        float sumA = 0.0f, sumB = 0.0f;
#pragma unroll
        for (int nt = 0; nt < 8; nt++) {
            float p0 = __expf(s[nt][0] - nmA);
            float p1 = __expf(s[nt][1] - nmA);
            float p2 = __expf(s[nt][2] - nmB);
            float p3 = __expf(s[nt][3] - nmB);
            s[nt][0] = p0; s[nt][1] = p1; s[nt][2] = p2; s[nt][3] = p3;
            sumA += p0 + p1;
            sumB += p2 + p3;
        }
        sumA += __shfl_xor_sync(0xffffffffu, sumA, 1);
        sumA += __shfl_xor_sync(0xffffffffu, sumA, 2);
        sumB += __shfl_xor_sync(0xffffffffu, sumB, 1);
        sumB += __shfl_xor_sync(0xffffffffu, sumB, 2);
        lA = lA * alA + sumA;
        lB = lB * alB + sumB;

#pragma unroll
        for (int nt = 0; nt < 8; nt++) {
            oacc[nt][0] *= alA; oacc[nt][1] *= alA;
            oacc[nt][2] *= alB; oacc[nt][3] *= alB;
        }

#pragma unroll
        for (int nt = 0; nt < 8; nt++) {
            *(float2*)&Pw[g * FST + nt * 8 + 2 * qd] =
                make_float2(tf32r(s[nt][0]), tf32r(s[nt][1]));
            *(float2*)&Pw[(g + 8) * FST + nt * 8 + 2 * qd] =
                make_float2(tf32r(s[nt][2]), tf32r(s[nt][3]));
        }
        __syncwarp();

#pragma unroll
        for (int kt = 0; kt < 8; kt++) {
            unsigned ap[4];
            ap[0] = __float_as_uint(Pw[g * FST + kt * 8 + qd]);
            ap[1] = __float_as_uint(Pw[(g + 8) * FST + kt * 8 + qd]);
            ap[2] = __float_as_uint(Pw[g * FST + kt * 8 + qd + 4]);
            ap[3] = __float_as_uint(Pw[(g + 8) * FST + kt * 8 + qd + 4]);
            unsigned vv[8][2];
#pragma unroll
            for (int nt = 0; nt < 8; nt++) {
                vv[nt][0] = __float_as_uint(Vs[(kt * 8 + qd) * VST + nt * 8 + g]);
                vv[nt][1] = __float_as_uint(Vs[(kt * 8 + qd + 4) * VST + nt * 8 + g]);
            }
#pragma unroll
            for (int nt = 0; nt < 8; nt++)
                mma8(oacc[nt], ap, vv[nt]);
        }
    }

    const float rAi = 1.0f / lA;
    const float rBi = 1.0f / lB;
#pragma unroll
    for (int nt = 0; nt < 8; nt++) {
        int c0 = nt * 8 + 2 * qd;
        *(float2*)&o[orow + (size_t)rA_loc * C_ + c0] =
            make_float2(tf32r(oacc[nt][0] * rAi), tf32r(oacc[nt][1] * rAi));
        *(float2*)&o[orow + (size_t)rB_loc * C_ + c0] =
            make_float2(tf32r(oacc[nt][2] * rBi), tf32r(oacc[nt][3] * rBi));
    }
}

// ---------------------------------------------------------------------------
extern "C" void kernel_launch(void* const* d_in, const int* in_sizes, int n_in,
                              void* d_out, int out_size)
{
    (void)in_sizes; (void)n_in; (void)out_size;
    const float* x  = (const float*)d_in[0];
    const float* Wq = (const float*)d_in[1];
    const float* Wk = (const float*)d_in[2];
    const float* Wv = (const float*)d_in[3];
    const float* Wo = (const float*)d_in[4];
    float* out = (float*)d_out;

    float *qkv, *ob, *xc, *wc;
    float2* tab;
    cudaGetSymbolAddress((void**)&qkv, g_qkv);
    cudaGetSymbolAddress((void**)&ob,  g_o);
    cudaGetSymbolAddress((void**)&xc,  g_xc);
    cudaGetSymbolAddress((void**)&wc,  g_wc);
    cudaGetSymbolAddress((void**)&tab, g_rope_tab);

    float* wqkv = wc;                          // [3C][C], K-permuted
    float* woc  = wc + 3 * (size_t)C_ * C_;    // plain tf32

    const int totg = XN8 + 4 * WN8;
    round_all_kernel<<<(totg + 255) / 256, 256>>>(x, Wq, Wk, Wv, Wo, xc, wc);
    rope_table_kernel<<<(T_ * 32 + 255) / 256, 256>>>(tab);

    const int qsmem = 6 * 4096 * (int)sizeof(float);        // 98,304 B
    cudaFuncSetAttribute(gemm_qkv,
                         cudaFuncAttributeMaxDynamicSharedMemorySize, qsmem);
    const int wsmem = 6 * 128 * GST * (int)sizeof(float);   // 110,592 B
    cudaFuncSetAttribute(gemm_wo,
                         cudaFuncAttributeMaxDynamicSharedMemorySize, wsmem);

    // fused QKV projection + RoPE epilogue (K-permuted operands)
    gemm_qkv<<<dim3(N3 / 128, M_ / 128), 128, qsmem>>>(
        xc, wqkv, qkv, tab, M_, N3, C_);

    const int fsmem = (64 * FST + 128 * FST + 128 * VST) * (int)sizeof(float);
    cudaFuncSetAttribute(flash_kernel,
                         cudaFuncAttributeMaxDynamicSharedMemorySize, fsmem);
    flash_kernel<<<dim3(T_ / 64, B_ * H_), 128, fsmem>>>(qkv, ob);

    gemm_wo<<<dim3(C_ / 128, M_ / 128), 128, wsmem>>>(
        ob, woc, out, M_, C_, C_);
}

// round 12
// speedup vs baseline: 1.5904x; 1.0401x over previous
#include <cuda_runtime.h>
#include <cuda_bf16.h>
#include <math.h>

#define B_  2
#define T_  2048
#define C_  1024
#define H_  16
#define D_  64
#define M_  (B_ * T_)     // 4096 rows
#define N3  (3 * C_)      // fused QKV width

// mma k-slot remap: hardware slots (qd, qd+4) hold LOGICAL elements
// (2qd, 2qd+1). A and B agree on the map -> product exact; fragment pairs
// become memory-adjacent -> LDS.64 with UNPERMUTED data.

// ---------------- scratch (device globals: no allocation allowed) ----------
__device__ __align__(128) float g_qkv[(size_t)M_ * N3];    // fused q|k|v
__device__ __align__(128) float g_o[(size_t)M_ * C_];
__device__ __align__(128) float g_xc[(size_t)M_ * C_];     // tf32-rounded x
__device__ __align__(128) float g_wc[4][(size_t)C_ * C_];  // tf32 Wq|Wk|Wv|Wo
__device__ __align__(128) float2 g_rope_tab[T_ * 32];

// ---------------- helpers ----------------------------------------------------
__device__ __forceinline__ void cp16(void* smem_dst, const void* gmem_src) {
    unsigned s = (unsigned)__cvta_generic_to_shared(smem_dst);
    asm volatile("cp.async.cg.shared.global [%0], [%1], 16;\n"
                 :: "r"(s), "l"(gmem_src));
}
#define CP_COMMIT()  asm volatile("cp.async.commit_group;\n")
#define CP_WAIT(n)   asm volatile("cp.async.wait_group %0;\n" :: "n"(n))

__device__ __forceinline__ float tf32r(float f) {
    unsigned u;
    asm("cvt.rna.tf32.f32 %0, %1;" : "=r"(u) : "f"(f));
    return __uint_as_float(u);
}
__device__ __forceinline__ void mma8(float* d, const unsigned* a,
                                     const unsigned* b) {
    asm volatile(
        "mma.sync.aligned.m16n8k8.row.col.f32.tf32.tf32.f32 "
        "{%0,%1,%2,%3}, {%4,%5,%6,%7}, {%8,%9}, {%0,%1,%2,%3};"
        : "+f"(d[0]), "+f"(d[1]), "+f"(d[2]), "+f"(d[3])
        : "r"(a[0]), "r"(a[1]), "r"(a[2]), "r"(a[3]),
          "r"(b[0]), "r"(b[1]));
}

// ---------------------------------------------------------------------------
// combined tf32 pre-round pass (plain; no permutation needed anymore)
// ---------------------------------------------------------------------------
#define XN4 (M_ * C_ / 4)
#define WN4 (C_ * C_ / 4)

__global__ __launch_bounds__(256) void round_all_kernel(
    const float* __restrict__ x,
    const float* __restrict__ Wq, const float* __restrict__ Wk,
    const float* __restrict__ Wv, const float* __restrict__ Wo,
    float* __restrict__ xc, float* __restrict__ wc)
{
    int i = blockIdx.x * blockDim.x + threadIdx.x;
    if (i >= XN4 + 4 * WN4) return;
    const float* src;
    float* dst;
    int idx;
    if (i < XN4) {
        src = x; dst = xc; idx = i;
    } else {
        int r = i - XN4;
        int which = r / WN4;
        idx = r - which * WN4;
        const float* ws[4] = {Wq, Wk, Wv, Wo};
        src = ws[which];
        dst = wc + (size_t)which * (C_ * C_);
    }
    float4 t = ((const float4*)src)[idx];
    t.x = tf32r(t.x); t.y = tf32r(t.y); t.z = tf32r(t.z); t.w = tf32r(t.w);
    ((float4*)dst)[idx] = t;
}

__global__ __launch_bounds__(256) void rope_table_kernel(float2* __restrict__ tab)
{
    int idx = blockIdx.x * blockDim.x + threadIdx.x;
    if (idx >= T_ * 32) return;
    int t = idx >> 5;
    int j = idx & 31;
    double inv = exp(-((double)(2 * j) / 64.0) * log(10000.0));
    double ang = (double)t * inv;
    tab[idx] = make_float2((float)cos(ang), (float)sin(ang));
}

// ---------------------------------------------------------------------------
// GEMM: Y[M,N] = A[M,K] @ B[N,K]^T, raw mma.sync m16n8k8 tf32, slot-remapped
// LDS.64 fragment loads. ST=32 unpadded + XOR swizzle ((row&3)<<3):
// conflict-free cp.async stores AND half-warp-phase-conflict-free LDS.64.
// 128x128 tile, 4 warps, BK=32, 3-stage, one barrier/iter, 2 CTAs/SM.
// ROPE=true: rotate q/k (even,odd) column pairs in the epilogue + tf32-round.
// ---------------------------------------------------------------------------
template <bool ROPE>
__global__ __launch_bounds__(128, 2) void gemm_tn(
    const float* __restrict__ A, const float* __restrict__ Bm,
    float* __restrict__ Y, const float2* __restrict__ tab,
    int M, int N, int K)
{
    extern __shared__ float sg[];
    float* As = sg;                    // 3 x 128 x 32
    float* Bs = sg + 3 * 4096;         // 3 x 128 x 32

    const int m0  = blockIdx.y * 128;
    const int n0  = blockIdx.x * 128;
    const int tid = threadIdx.x;
    const int w   = tid >> 5;
    const int wm  = w >> 1;
    const int wn  = w & 1;
    const int l   = tid & 31;
    const int g   = l >> 2;
    const int qd  = l & 3;
    const int swz = (g & 3) << 3;      // XOR term, 8-float granularity

    float acc[4][8][4];
#pragma unroll
    for (int i = 0; i < 4; i++)
#pragma unroll
        for (int j = 0; j < 8; j++)
#pragma unroll
            for (int e = 0; e < 4; e++) acc[i][j][e] = 0.0f;

    auto load_stage = [&](int buf, int kc) {
#pragma unroll
        for (int i = tid; i < 1024; i += 128) {
            int r = i >> 3;
            int c = i & 7;
            int d = (4 * c) ^ ((r & 3) << 3);
            cp16(&As[buf * 4096 + r * 32 + d],
                 &A[(size_t)(m0 + r) * K + kc + 4 * c]);
            cp16(&Bs[buf * 4096 + r * 32 + d],
                 &Bm[(size_t)(n0 + r) * K + kc + 4 * c]);
        }
    };

    load_stage(0, 0);
    CP_COMMIT();
    load_stage(1, 32);
    CP_COMMIT();

    const int NIT = K / 32;
    for (int it = 0; it < NIT; it++) {
        if (it < NIT - 1) { CP_WAIT(1); } else { CP_WAIT(0); }
        __syncthreads();
        if (it + 2 < NIT) {
            load_stage((it + 2) % 3, (it + 2) * 32);
            CP_COMMIT();
        }

        const float* Ab = &As[(it % 3) * 4096 + (wm * 64) * 32];
        const float* Bb = &Bs[(it % 3) * 4096 + (wn * 64) * 32];

#pragma unroll
        for (int k8 = 0; k8 < 4; k8++) {
            const int ko = (8 * k8 + 2 * qd) ^ swz;
            unsigned av[4][4];
#pragma unroll
            for (int i = 0; i < 4; i++) {
                float2 va = *(const float2*)&Ab[(i * 16 + g)     * 32 + ko];
                float2 vc = *(const float2*)&Ab[(i * 16 + g + 8) * 32 + ko];
                av[i][0] = __float_as_uint(va.x);
                av[i][1] = __float_as_uint(vc.x);
                av[i][2] = __float_as_uint(va.y);
                av[i][3] = __float_as_uint(vc.y);
            }
            unsigned bv[8][2];
#pragma unroll
            for (int j = 0; j < 8; j++) {
                float2 vb = *(const float2*)&Bb[(j * 8 + g) * 32 + ko];
                bv[j][0] = __float_as_uint(vb.x);
                bv[j][1] = __float_as_uint(vb.y);
            }
#pragma unroll
            for (int i = 0; i < 4; i++)
#pragma unroll
                for (int j = 0; j < 8; j++)
                    mma8(acc[i][j], av[i], bv[j]);
        }
    }

    // epilogue (RoPE fused for q/k columns when ROPE=true)
#pragma unroll
    for (int i = 0; i < 4; i++) {
        const int rA = m0 + wm * 64 + i * 16 + g;
        const int rB = rA + 8;
        const size_t rowA = (size_t)rA * N;
        const size_t rowB = (size_t)rB * N;
        const int tA = rA & (T_ - 1);
        const int tB = rB & (T_ - 1);
#pragma unroll
        for (int j = 0; j < 8; j++) {
            const int col = n0 + wn * 64 + j * 8 + 2 * qd;
            float e0 = acc[i][j][0], o0 = acc[i][j][1];
            float e1 = acc[i][j][2], o1 = acc[i][j][3];
            if (ROPE) {
                if (col < 2 * C_) {
                    const int jj = (col & (D_ - 1)) >> 1;
                    float2 csA = tab[tA * 32 + jj];
                    float2 csB = tab[tB * 32 + jj];
                    float ne0 = e0 * csA.x - o0 * csA.y;
                    float no0 = e0 * csA.y + o0 * csA.x;
                    float ne1 = e1 * csB.x - o1 * csB.y;
                    float no1 = e1 * csB.y + o1 * csB.x;
                    e0 = ne0; o0 = no0; e1 = ne1; o1 = no1;
                }
                e0 = tf32r(e0); o0 = tf32r(o0);
                e1 = tf32r(e1); o1 = tf32r(o1);
            }
            *(float2*)&Y[rowA + col] = make_float2(e0, o0);
            *(float2*)&Y[rowB + col] = make_float2(e1, o1);
        }
    }
}

// ---------------------------------------------------------------------------
// Flash attention (causal), FA-2 style, slot-remapped LDS.64 fragment loads.
// BM=64 (4 warps x 16 rows), BN=64, D=64, mma.sync m16n8k8 tf32.
// FST=72 (K/Q/P: float2 loads conflict-free per half-warp phase),
// VST=68 (V: scalar row-2qd loads conflict-free). 2 CTAs/SM.
// ---------------------------------------------------------------------------
#define FST 72
#define VST 68

__global__ __launch_bounds__(128, 2) void flash_kernel(
    const float* __restrict__ qkv, float* __restrict__ o)
{
    extern __shared__ float sm[];
    float* QP = sm;                     // 64*FST: Q staging, then P strips
    float* Kb = QP + 64 * FST;          // 2 x 64*FST
    float* Vb = Kb + 128 * FST;         // 2 x 64*VST

    const int bh  = blockIdx.y;
    const int b   = bh >> 4;
    const int h   = bh & 15;
    const int q0  = (gridDim.x - 1 - blockIdx.x) * 64;
    const int tid = threadIdx.x;
    const int w   = tid >> 5;
    const int l   = tid & 31;
    const int g   = l >> 2;
    const int qd  = l & 3;
    const float scale = 0.125f;

    const size_t qbase = (size_t)(b * T_ + q0) * N3 + h * D_;
    const size_t orow  = (size_t)(b * T_ + q0) * C_ + h * D_;

    auto kv_load = [&](int buf, int n0) {
        const size_t kbase = (size_t)(b * T_ + n0) * N3 + h * D_ + C_;
#pragma unroll
        for (int i = tid; i < 1024; i += 128) {
            int r = i >> 4, c = (i & 15) << 2;
            cp16(&Kb[buf * 64 * FST + r * FST + c],
                 &qkv[kbase + (size_t)r * N3 + c]);
            cp16(&Vb[buf * 64 * VST + r * VST + c],
                 &qkv[kbase + (size_t)r * N3 + C_ + c]);
        }
    };

    kv_load(0, 0);
    CP_COMMIT();

    for (int i = tid; i < 1024; i += 128) {
        int r = i >> 4, c = (i & 15) << 2;
        float4 t4 = *(const float4*)&qkv[qbase + (size_t)r * N3 + c];
        t4.x *= scale; t4.y *= scale; t4.z *= scale; t4.w *= scale;
        *(float4*)&QP[r * FST + c] = t4;
    }
    __syncthreads();

    // Q fragments via slot-remapped float2 loads
    unsigned aq[8][4];
    float* Pw = QP + w * 16 * FST;
#pragma unroll
    for (int kt = 0; kt < 8; kt++) {
        float2 va = *(const float2*)&Pw[g * FST + kt * 8 + 2 * qd];
        float2 vb = *(const float2*)&Pw[(g + 8) * FST + kt * 8 + 2 * qd];
        aq[kt][0] = __float_as_uint(va.x);
        aq[kt][1] = __float_as_uint(vb.x);
        aq[kt][2] = __float_as_uint(va.y);
        aq[kt][3] = __float_as_uint(vb.y);
    }
    __syncwarp();

    float oacc[8][4];
#pragma unroll
    for (int nt = 0; nt < 8; nt++)
#pragma unroll
        for (int j = 0; j < 4; j++) oacc[nt][j] = 0.0f;
    float mA = -INFINITY, mB = -INFINITY, lA = 0.0f, lB = 0.0f;

    const int rA_loc = w * 16 + g;
    const int rB_loc = rA_loc + 8;

    for (int n0 = 0; n0 <= q0; n0 += 64) {
        const int buf = (n0 >> 6) & 1;
        CP_WAIT(0);
        __syncthreads();
        if (n0 + 64 <= q0) {
            kv_load(buf ^ 1, n0 + 64);
            CP_COMMIT();
        }

        const float* Ks = &Kb[buf * 64 * FST];
        const float* Vs = &Vb[buf * 64 * VST];

        float s[8][4];
#pragma unroll
        for (int nt = 0; nt < 8; nt++)
#pragma unroll
            for (int j = 0; j < 4; j++) s[nt][j] = 0.0f;

        // S = Q K^T, K fragments via float2 (slot-remapped)
#pragma unroll
        for (int kt = 0; kt < 8; kt++) {
            unsigned bb[8][2];
#pragma unroll
            for (int nt = 0; nt < 8; nt++) {
                float2 kb = *(const float2*)&Ks[(nt * 8 + g) * FST + kt * 8 + 2 * qd];
                bb[nt][0] = __float_as_uint(kb.x);
                bb[nt][1] = __float_as_uint(kb.y);
            }
#pragma unroll
            for (int nt = 0; nt < 8; nt++)
                mma8(s[nt], aq[kt], bb[nt]);
        }

        if (n0 == q0) {
#pragma unroll
            for (int nt = 0; nt < 8; nt++) {
                int c0 = nt * 8 + 2 * qd;
                if (c0     > rA_loc) s[nt][0] = -INFINITY;
                if (c0 + 1 > rA_loc) s[nt][1] = -INFINITY;
                if (c0     > rB_loc) s[nt][2] = -INFINITY;
                if (c0 + 1 > rB_loc) s[nt][3] = -INFINITY;
            }
        }

        float mxA = -INFINITY, mxB = -INFINITY;
#pragma unroll
        for (int nt = 0; nt < 8; nt++) {
            mxA = fmaxf(mxA, fmaxf(s[nt][0], s[nt][1]));
            mxB = fmaxf(mxB, fmaxf(s[nt][2], s[nt][3]));
        }
        mxA = fmaxf(mxA, __shfl_xor_sync(0xffffffffu, mxA, 1));
        mxA = fmaxf(mxA, __shfl_xor_sync(0xffffffffu, mxA, 2));
        mxB = fmaxf(mxB, __shfl_xor_sync(0xffffffffu, mxB, 1));
        mxB = fmaxf(mxB, __shfl_xor_sync(0xffffffffu, mxB, 2));

        float nmA = fmaxf(mA, mxA);
        float nmB = fmaxf(mB, mxB);
        float alA = __expf(mA - nmA);
        float alB = __expf(mB - nmB);
        mA = nmA; mB = nmB;

        float sumA = 0.0f, sumB = 0.0f;
#pragma unroll
        for (int nt = 0; nt < 8; nt++) {
            float p0 = __expf(s[nt][0] - nmA);
            float p1 = __expf(s[nt][1] - nmA);
            float p2 = __expf(s[nt][2] - nmB);
            float p3 = __expf(s[nt][3] - nmB);
            s[nt][0] = p0; s[nt][1] = p1; s[nt][2] = p2; s[nt][3] = p3;
            sumA += p0 + p1;
            sumB += p2 + p3;
        }
        sumA += __shfl_xor_sync(0xffffffffu, sumA, 1);
        sumA += __shfl_xor_sync(0xffffffffu, sumA, 2);
        sumB += __shfl_xor_sync(0xffffffffu, sumB, 1);
        sumB += __shfl_xor_sync(0xffffffffu, sumB, 2);
        lA = lA * alA + sumA;
        lB = lB * alB + sumB;

#pragma unroll
        for (int nt = 0; nt < 8; nt++) {
            oacc[nt][0] *= alA; oacc[nt][1] *= alA;
            oacc[nt][2] *= alB; oacc[nt][3] *= alB;
        }

        // P to warp-private strip (float2, layout unchanged)
#pragma unroll
        for (int nt = 0; nt < 8; nt++) {
            *(float2*)&Pw[g * FST + nt * 8 + 2 * qd] =
                make_float2(tf32r(s[nt][0]), tf32r(s[nt][1]));
            *(float2*)&Pw[(g + 8) * FST + nt * 8 + 2 * qd] =
                make_float2(tf32r(s[nt][2]), tf32r(s[nt][3]));
        }
        __syncwarp();

        // O += P V : P via float2 (slot-remapped), V rows 2qd / 2qd+1
#pragma unroll
        for (int kt = 0; kt < 8; kt++) {
            unsigned ap[4];
            {
                float2 pa = *(const float2*)&Pw[g * FST + kt * 8 + 2 * qd];
                float2 pb = *(const float2*)&Pw[(g + 8) * FST + kt * 8 + 2 * qd];
                ap[0] = __float_as_uint(pa.x);
                ap[1] = __float_as_uint(pb.x);
                ap[2] = __float_as_uint(pa.y);
                ap[3] = __float_as_uint(pb.y);
            }
            unsigned vv[8][2];
#pragma unroll
            for (int nt = 0; nt < 8; nt++) {
                vv[nt][0] = __float_as_uint(Vs[(kt * 8 + 2 * qd)     * VST + nt * 8 + g]);
                vv[nt][1] = __float_as_uint(Vs[(kt * 8 + 2 * qd + 1) * VST + nt * 8 + g]);
            }
#pragma unroll
            for (int nt = 0; nt < 8; nt++)
                mma8(oacc[nt], ap, vv[nt]);
        }
    }

    const float rAi = 1.0f / lA;
    const float rBi = 1.0f / lB;
#pragma unroll
    for (int nt = 0; nt < 8; nt++) {
        int c0 = nt * 8 + 2 * qd;
        *(float2*)&o[orow + (size_t)rA_loc * C_ + c0] =
            make_float2(tf32r(oacc[nt][0] * rAi), tf32r(oacc[nt][1] * rAi));
        *(float2*)&o[orow + (size_t)rB_loc * C_ + c0] =
            make_float2(tf32r(oacc[nt][2] * rBi), tf32r(oacc[nt][3] * rBi));
    }
}

// ---------------------------------------------------------------------------
extern "C" void kernel_launch(void* const* d_in, const int* in_sizes, int n_in,
                              void* d_out, int out_size)
{
    (void)in_sizes; (void)n_in; (void)out_size;
    const float* x  = (const float*)d_in[0];
    const float* Wq = (const float*)d_in[1];
    const float* Wk = (const float*)d_in[2];
    const float* Wv = (const float*)d_in[3];
    const float* Wo = (const float*)d_in[4];
    float* out = (float*)d_out;

    float *qkv, *ob, *xc, *wc;
    float2* tab;
    cudaGetSymbolAddress((void**)&qkv, g_qkv);
    cudaGetSymbolAddress((void**)&ob,  g_o);
    cudaGetSymbolAddress((void**)&xc,  g_xc);
    cudaGetSymbolAddress((void**)&wc,  g_wc);
    cudaGetSymbolAddress((void**)&tab, g_rope_tab);

    float* wqkv = wc;                          // [3C][C], contiguous
    float* woc  = wc + 3 * (size_t)C_ * C_;

    const int totn4 = XN4 + 4 * WN4;
    round_all_kernel<<<(totn4 + 255) / 256, 256>>>(x, Wq, Wk, Wv, Wo, xc, wc);
    rope_table_kernel<<<(T_ * 32 + 255) / 256, 256>>>(tab);

    const int gsmem = 6 * 4096 * (int)sizeof(float);        // 98,304 B
    cudaFuncSetAttribute(gemm_tn<true>,
                         cudaFuncAttributeMaxDynamicSharedMemorySize, gsmem);
    cudaFuncSetAttribute(gemm_tn<false>,
                         cudaFuncAttributeMaxDynamicSharedMemorySize, gsmem);

    // fused QKV projection + RoPE epilogue
    gemm_tn<true><<<dim3(N3 / 128, M_ / 128), 128, gsmem>>>(
        xc, wqkv, qkv, tab, M_, N3, C_);

    const int fsmem = (64 * FST + 128 * FST + 128 * VST) * (int)sizeof(float);
    cudaFuncSetAttribute(flash_kernel,
                         cudaFuncAttributeMaxDynamicSharedMemorySize, fsmem);
    flash_kernel<<<dim3(T_ / 64, B_ * H_), 128, fsmem>>>(qkv, ob);

    gemm_tn<false><<<dim3(C_ / 128, M_ / 128), 128, gsmem>>>(
        ob, woc, out, tab, M_, C_, C_);
}

// round 13
// speedup vs baseline: 1.6185x; 1.0177x over previous
#include <cuda_runtime.h>
#include <cuda_bf16.h>
#include <math.h>

#define B_  2
#define T_  2048
#define C_  1024
#define H_  16
#define D_  64
#define M_  (B_ * T_)     // 4096 rows
#define N3  (3 * C_)      // fused QKV width

// mma k-slot remap: hardware slots (qd, qd+4) hold LOGICAL elements
// (2qd, 2qd+1). A and B agree on the map -> product exact; fragment pairs
// become memory-adjacent -> LDS.64 with UNPERMUTED data. In flash, the
// S-accumulator registers directly ARE the PV A-fragment under this map
// (no P smem round-trip).

// ---------------- scratch (device globals: no allocation allowed) ----------
__device__ __align__(128) float g_qkv[(size_t)M_ * N3];    // fused q|k|v
__device__ __align__(128) float g_o[(size_t)M_ * C_];
__device__ __align__(128) float g_xc[(size_t)M_ * C_];     // tf32-rounded x
__device__ __align__(128) float g_wc[4][(size_t)C_ * C_];  // tf32 Wq|Wk|Wv|Wo
__device__ __align__(128) float2 g_rope_tab[T_ * 32];

// ---------------- helpers ----------------------------------------------------
__device__ __forceinline__ void cp16(void* smem_dst, const void* gmem_src) {
    unsigned s = (unsigned)__cvta_generic_to_shared(smem_dst);
    asm volatile("cp.async.cg.shared.global [%0], [%1], 16;\n"
                 :: "r"(s), "l"(gmem_src));
}
#define CP_COMMIT()  asm volatile("cp.async.commit_group;\n")
#define CP_WAIT(n)   asm volatile("cp.async.wait_group %0;\n" :: "n"(n))

__device__ __forceinline__ float tf32r(float f) {
    unsigned u;
    asm("cvt.rna.tf32.f32 %0, %1;" : "=r"(u) : "f"(f));
    return __uint_as_float(u);
}
__device__ __forceinline__ void mma8(float* d, const unsigned* a,
                                     const unsigned* b) {
    asm volatile(
        "mma.sync.aligned.m16n8k8.row.col.f32.tf32.tf32.f32 "
        "{%0,%1,%2,%3}, {%4,%5,%6,%7}, {%8,%9}, {%0,%1,%2,%3};"
        : "+f"(d[0]), "+f"(d[1]), "+f"(d[2]), "+f"(d[3])
        : "r"(a[0]), "r"(a[1]), "r"(a[2]), "r"(a[3]),
          "r"(b[0]), "r"(b[1]));
}

// ---------------------------------------------------------------------------
// combined prep pass: tf32 rounding for x + 4 weights, AND the RoPE table,
// all in ONE launch.
// ---------------------------------------------------------------------------
#define XN4 (M_ * C_ / 4)
#define WN4 (C_ * C_ / 4)
#define PREP_TOT (XN4 + 4 * WN4 + T_ * 32)

__global__ __launch_bounds__(256) void prep_kernel(
    const float* __restrict__ x,
    const float* __restrict__ Wq, const float* __restrict__ Wk,
    const float* __restrict__ Wv, const float* __restrict__ Wo,
    float* __restrict__ xc, float* __restrict__ wc,
    float2* __restrict__ tab)
{
    int i = blockIdx.x * blockDim.x + threadIdx.x;
    if (i >= PREP_TOT) return;
    if (i >= XN4 + 4 * WN4) {
        int idx = i - (XN4 + 4 * WN4);      // rope table entry
        int t = idx >> 5;
        int j = idx & 31;
        double inv = exp(-((double)(2 * j) / 64.0) * log(10000.0));
        double ang = (double)t * inv;
        tab[idx] = make_float2((float)cos(ang), (float)sin(ang));
        return;
    }
    const float* src;
    float* dst;
    int idx;
    if (i < XN4) {
        src = x; dst = xc; idx = i;
    } else {
        int r = i - XN4;
        int which = r / WN4;
        idx = r - which * WN4;
        const float* ws[4] = {Wq, Wk, Wv, Wo};
        src = ws[which];
        dst = wc + (size_t)which * (C_ * C_);
    }
    float4 t = ((const float4*)src)[idx];
    t.x = tf32r(t.x); t.y = tf32r(t.y); t.z = tf32r(t.z); t.w = tf32r(t.w);
    ((float4*)dst)[idx] = t;
}

// ---------------------------------------------------------------------------
// GEMM: Y[M,N] = A[M,K] @ B[N,K]^T, raw mma.sync m16n8k8 tf32, slot-remapped
// LDS.64 fragment loads. ST=32 unpadded + XOR swizzle ((row&3)<<3).
// 128x128 tile, 4 warps, BK=32, 3-stage, one barrier/iter, 2 CTAs/SM.
// ROPE=true: rotate q/k (even,odd) column pairs in the epilogue + tf32-round.
// ---------------------------------------------------------------------------
template <bool ROPE>
__global__ __launch_bounds__(128, 2) void gemm_tn(
    const float* __restrict__ A, const float* __restrict__ Bm,
    float* __restrict__ Y, const float2* __restrict__ tab,
    int M, int N, int K)
{
    extern __shared__ float sg[];
    float* As = sg;                    // 3 x 128 x 32
    float* Bs = sg + 3 * 4096;         // 3 x 128 x 32

    const int m0  = blockIdx.y * 128;
    const int n0  = blockIdx.x * 128;
    const int tid = threadIdx.x;
    const int w   = tid >> 5;
    const int wm  = w >> 1;
    const int wn  = w & 1;
    const int l   = tid & 31;
    const int g   = l >> 2;
    const int qd  = l & 3;
    const int swz = (g & 3) << 3;

    float acc[4][8][4];
#pragma unroll
    for (int i = 0; i < 4; i++)
#pragma unroll
        for (int j = 0; j < 8; j++)
#pragma unroll
            for (int e = 0; e < 4; e++) acc[i][j][e] = 0.0f;

    auto load_stage = [&](int buf, int kc) {
#pragma unroll
        for (int i = tid; i < 1024; i += 128) {
            int r = i >> 3;
            int c = i & 7;
            int d = (4 * c) ^ ((r & 3) << 3);
            cp16(&As[buf * 4096 + r * 32 + d],
                 &A[(size_t)(m0 + r) * K + kc + 4 * c]);
            cp16(&Bs[buf * 4096 + r * 32 + d],
                 &Bm[(size_t)(n0 + r) * K + kc + 4 * c]);
        }
    };

    load_stage(0, 0);
    CP_COMMIT();
    load_stage(1, 32);
    CP_COMMIT();

    const int NIT = K / 32;
    for (int it = 0; it < NIT; it++) {
        if (it < NIT - 1) { CP_WAIT(1); } else { CP_WAIT(0); }
        __syncthreads();
        if (it + 2 < NIT) {
            load_stage((it + 2) % 3, (it + 2) * 32);
            CP_COMMIT();
        }

        const float* Ab = &As[(it % 3) * 4096 + (wm * 64) * 32];
        const float* Bb = &Bs[(it % 3) * 4096 + (wn * 64) * 32];

#pragma unroll
        for (int k8 = 0; k8 < 4; k8++) {
            const int ko = (8 * k8 + 2 * qd) ^ swz;
            unsigned av[4][4];
#pragma unroll
            for (int i = 0; i < 4; i++) {
                float2 va = *(const float2*)&Ab[(i * 16 + g)     * 32 + ko];
                float2 vc = *(const float2*)&Ab[(i * 16 + g + 8) * 32 + ko];
                av[i][0] = __float_as_uint(va.x);
                av[i][1] = __float_as_uint(vc.x);
                av[i][2] = __float_as_uint(va.y);
                av[i][3] = __float_as_uint(vc.y);
            }
            unsigned bv[8][2];
#pragma unroll
            for (int j = 0; j < 8; j++) {
                float2 vb = *(const float2*)&Bb[(j * 8 + g) * 32 + ko];
                bv[j][0] = __float_as_uint(vb.x);
                bv[j][1] = __float_as_uint(vb.y);
            }
#pragma unroll
            for (int i = 0; i < 4; i++)
#pragma unroll
                for (int j = 0; j < 8; j++)
                    mma8(acc[i][j], av[i], bv[j]);
        }
    }

#pragma unroll
    for (int i = 0; i < 4; i++) {
        const int rA = m0 + wm * 64 + i * 16 + g;
        const int rB = rA + 8;
        const size_t rowA = (size_t)rA * N;
        const size_t rowB = (size_t)rB * N;
        const int tA = rA & (T_ - 1);
        const int tB = rB & (T_ - 1);
#pragma unroll
        for (int j = 0; j < 8; j++) {
            const int col = n0 + wn * 64 + j * 8 + 2 * qd;
            float e0 = acc[i][j][0], o0 = acc[i][j][1];
            float e1 = acc[i][j][2], o1 = acc[i][j][3];
            if (ROPE) {
                if (col < 2 * C_) {
                    const int jj = (col & (D_ - 1)) >> 1;
                    float2 csA = tab[tA * 32 + jj];
                    float2 csB = tab[tB * 32 + jj];
                    float ne0 = e0 * csA.x - o0 * csA.y;
                    float no0 = e0 * csA.y + o0 * csA.x;
                    float ne1 = e1 * csB.x - o1 * csB.y;
                    float no1 = e1 * csB.y + o1 * csB.x;
                    e0 = ne0; o0 = no0; e1 = ne1; o1 = no1;
                }
                e0 = tf32r(e0); o0 = tf32r(o0);
                e1 = tf32r(e1); o1 = tf32r(o1);
            }
            *(float2*)&Y[rowA + col] = make_float2(e0, o0);
            *(float2*)&Y[rowB + col] = make_float2(e1, o1);
        }
    }
}

// ---------------------------------------------------------------------------
// Flash attention (causal), FA-2 style, slot-remapped fragments.
// BM=64 (4 warps x 16 rows), BN=64, D=64, mma.sync m16n8k8 tf32.
// P NEVER touches smem: S-accumulator registers are reused directly as the
// PV A-fragment (layout identity under the slot remap), tf32-rounded in regs.
// FST=72 (Q/K float2 loads), VST=68 (V scalar loads). 2 CTAs/SM.
// ---------------------------------------------------------------------------
#define FST 72
#define VST 68

__global__ __launch_bounds__(128, 2) void flash_kernel(
    const float* __restrict__ qkv, float* __restrict__ o)
{
    extern __shared__ float sm[];
    float* Qs = sm;                     // 64*FST: Q staging
    float* Kb = Qs + 64 * FST;          // 2 x 64*FST
    float* Vb = Kb + 128 * FST;         // 2 x 64*VST

    const int bh  = blockIdx.y;
    const int b   = bh >> 4;
    const int h   = bh & 15;
    const int q0  = (gridDim.x - 1 - blockIdx.x) * 64;
    const int tid = threadIdx.x;
    const int w   = tid >> 5;
    const int l   = tid & 31;
    const int g   = l >> 2;
    const int qd  = l & 3;
    const float scale = 0.125f;

    const size_t qbase = (size_t)(b * T_ + q0) * N3 + h * D_;
    const size_t orow  = (size_t)(b * T_ + q0) * C_ + h * D_;

    auto kv_load = [&](int buf, int n0) {
        const size_t kbase = (size_t)(b * T_ + n0) * N3 + h * D_ + C_;
#pragma unroll
        for (int i = tid; i < 1024; i += 128) {
            int r = i >> 4, c = (i & 15) << 2;
            cp16(&Kb[buf * 64 * FST + r * FST + c],
                 &qkv[kbase + (size_t)r * N3 + c]);
            cp16(&Vb[buf * 64 * VST + r * VST + c],
                 &qkv[kbase + (size_t)r * N3 + C_ + c]);
        }
    };

    kv_load(0, 0);
    CP_COMMIT();

    for (int i = tid; i < 1024; i += 128) {
        int r = i >> 4, c = (i & 15) << 2;
        float4 t4 = *(const float4*)&qkv[qbase + (size_t)r * N3 + c];
        t4.x *= scale; t4.y *= scale; t4.z *= scale; t4.w *= scale;
        *(float4*)&Qs[r * FST + c] = t4;
    }
    __syncthreads();

    // Q fragments via slot-remapped float2 loads (warp-private rows)
    unsigned aq[8][4];
    const float* Qw = Qs + w * 16 * FST;
#pragma unroll
    for (int kt = 0; kt < 8; kt++) {
        float2 va = *(const float2*)&Qw[g * FST + kt * 8 + 2 * qd];
        float2 vb = *(const float2*)&Qw[(g + 8) * FST + kt * 8 + 2 * qd];
        aq[kt][0] = __float_as_uint(va.x);
        aq[kt][1] = __float_as_uint(vb.x);
        aq[kt][2] = __float_as_uint(va.y);
        aq[kt][3] = __float_as_uint(vb.y);
    }

    float oacc[8][4];
#pragma unroll
    for (int nt = 0; nt < 8; nt++)
#pragma unroll
        for (int j = 0; j < 4; j++) oacc[nt][j] = 0.0f;
    float mA = -INFINITY, mB = -INFINITY, lA = 0.0f, lB = 0.0f;

    const int rA_loc = w * 16 + g;
    const int rB_loc = rA_loc + 8;

    for (int n0 = 0; n0 <= q0; n0 += 64) {
        const int buf = (n0 >> 6) & 1;
        CP_WAIT(0);
        __syncthreads();
        if (n0 + 64 <= q0) {
            kv_load(buf ^ 1, n0 + 64);
            CP_COMMIT();
        }

        const float* Ks = &Kb[buf * 64 * FST];
        const float* Vs = &Vb[buf * 64 * VST];

        float s[8][4];
#pragma unroll
        for (int nt = 0; nt < 8; nt++)
#pragma unroll
            for (int j = 0; j < 4; j++) s[nt][j] = 0.0f;

        // S = Q K^T, K fragments via float2 (slot-remapped)
#pragma unroll
        for (int kt = 0; kt < 8; kt++) {
            unsigned bb[8][2];
#pragma unroll
            for (int nt = 0; nt < 8; nt++) {
                float2 kb = *(const float2*)&Ks[(nt * 8 + g) * FST + kt * 8 + 2 * qd];
                bb[nt][0] = __float_as_uint(kb.x);
                bb[nt][1] = __float_as_uint(kb.y);
            }
#pragma unroll
            for (int nt = 0; nt < 8; nt++)
                mma8(s[nt], aq[kt], bb[nt]);
        }

        if (n0 == q0) {
#pragma unroll
            for (int nt = 0; nt < 8; nt++) {
                int c0 = nt * 8 + 2 * qd;
                if (c0     > rA_loc) s[nt][0] = -INFINITY;
                if (c0 + 1 > rA_loc) s[nt][1] = -INFINITY;
                if (c0     > rB_loc) s[nt][2] = -INFINITY;
                if (c0 + 1 > rB_loc) s[nt][3] = -INFINITY;
            }
        }

        float mxA = -INFINITY, mxB = -INFINITY;
#pragma unroll
        for (int nt = 0; nt < 8; nt++) {
            mxA = fmaxf(mxA, fmaxf(s[nt][0], s[nt][1]));
            mxB = fmaxf(mxB, fmaxf(s[nt][2], s[nt][3]));
        }
        mxA = fmaxf(mxA, __shfl_xor_sync(0xffffffffu, mxA, 1));
        mxA = fmaxf(mxA, __shfl_xor_sync(0xffffffffu, mxA, 2));
        mxB = fmaxf(mxB, __shfl_xor_sync(0xffffffffu, mxB, 1));
        mxB = fmaxf(mxB, __shfl_xor_sync(0xffffffffu, mxB, 2));

        float nmA = fmaxf(mA, mxA);
        float nmB = fmaxf(mB, mxB);
        float alA = __expf(mA - nmA);
        float alB = __expf(mB - nmB);
        mA = nmA; mB = nmB;

        float sumA = 0.0f, sumB = 0.0f;
#pragma unroll
        for (int nt = 0; nt < 8; nt++) {
            float p0 = __expf(s[nt][0] - nmA);
            float p1 = __expf(s[nt][1] - nmA);
            float p2 = __expf(s[nt][2] - nmB);
            float p3 = __expf(s[nt][3] - nmB);
            s[nt][0] = p0; s[nt][1] = p1; s[nt][2] = p2; s[nt][3] = p3;
            sumA += p0 + p1;
            sumB += p2 + p3;
        }
        sumA += __shfl_xor_sync(0xffffffffu, sumA, 1);
        sumA += __shfl_xor_sync(0xffffffffu, sumA, 2);
        sumB += __shfl_xor_sync(0xffffffffu, sumB, 1);
        sumB += __shfl_xor_sync(0xffffffffu, sumB, 2);
        lA = lA * alA + sumA;
        lB = lB * alB + sumB;

#pragma unroll
        for (int nt = 0; nt < 8; nt++) {
            oacc[nt][0] *= alA; oacc[nt][1] *= alA;
            oacc[nt][2] *= alB; oacc[nt][3] *= alB;
        }

        // O += P V : P comes STRAIGHT from the S accumulators (layout
        // identity under the slot remap), tf32-rounded in registers.
#pragma unroll
        for (int kt = 0; kt < 8; kt++) {
            unsigned ap[4];
            ap[0] = __float_as_uint(tf32r(s[kt][0]));
            ap[1] = __float_as_uint(tf32r(s[kt][2]));
            ap[2] = __float_as_uint(tf32r(s[kt][1]));
            ap[3] = __float_as_uint(tf32r(s[kt][3]));
            unsigned vv[8][2];
#pragma unroll
            for (int nt = 0; nt < 8; nt++) {
                vv[nt][0] = __float_as_uint(Vs[(kt * 8 + 2 * qd)     * VST + nt * 8 + g]);
                vv[nt][1] = __float_as_uint(Vs[(kt * 8 + 2 * qd + 1) * VST + nt * 8 + g]);
            }
#pragma unroll
            for (int nt = 0; nt < 8; nt++)
                mma8(oacc[nt], ap, vv[nt]);
        }
    }

    const float rAi = 1.0f / lA;
    const float rBi = 1.0f / lB;
#pragma unroll
    for (int nt = 0; nt < 8; nt++) {
        int c0 = nt * 8 + 2 * qd;
        *(float2*)&o[orow + (size_t)rA_loc * C_ + c0] =
            make_float2(tf32r(oacc[nt][0] * rAi), tf32r(oacc[nt][1] * rAi));
        *(float2*)&o[orow + (size_t)rB_loc * C_ + c0] =
            make_float2(tf32r(oacc[nt][2] * rBi), tf32r(oacc[nt][3] * rBi));
    }
}

// ---------------------------------------------------------------------------
extern "C" void kernel_launch(void* const* d_in, const int* in_sizes, int n_in,
                              void* d_out, int out_size)
{
    (void)in_sizes; (void)n_in; (void)out_size;
    const float* x  = (const float*)d_in[0];
    const float* Wq = (const float*)d_in[1];
    const float* Wk = (const float*)d_in[2];
    const float* Wv = (const float*)d_in[3];
    const float* Wo = (const float*)d_in[4];
    float* out = (float*)d_out;

    float *qkv, *ob, *xc, *wc;
    float2* tab;
    cudaGetSymbolAddress((void**)&qkv, g_qkv);
    cudaGetSymbolAddress((void**)&ob,  g_o);
    cudaGetSymbolAddress((void**)&xc,  g_xc);
    cudaGetSymbolAddress((void**)&wc,  g_wc);
    cudaGetSymbolAddress((void**)&tab, g_rope_tab);

    float* wqkv = wc;                          // [3C][C], contiguous
    float* woc  = wc + 3 * (size_t)C_ * C_;

    prep_kernel<<<(PREP_TOT + 255) / 256, 256>>>(x, Wq, Wk, Wv, Wo,
                                                 xc, wc, tab);

    const int gsmem = 6 * 4096 * (int)sizeof(float);        // 98,304 B
    cudaFuncSetAttribute(gemm_tn<true>,
                         cudaFuncAttributeMaxDynamicSharedMemorySize, gsmem);
    cudaFuncSetAttribute(gemm_tn<false>,
                         cudaFuncAttributeMaxDynamicSharedMemorySize, gsmem);

    // fused QKV projection + RoPE epilogue
    gemm_tn<true><<<dim3(N3 / 128, M_ / 128), 128, gsmem>>>(
        xc, wqkv, qkv, tab, M_, N3, C_);

    const int fsmem = (64 * FST + 128 * FST + 128 * VST) * (int)sizeof(float);
    cudaFuncSetAttribute(flash_kernel,
                         cudaFuncAttributeMaxDynamicSharedMemorySize, fsmem);
    flash_kernel<<<dim3(T_ / 64, B_ * H_), 128, fsmem>>>(qkv, ob);

    gemm_tn<false><<<dim3(C_ / 128, M_ / 128), 128, gsmem>>>(
        ob, woc, out, tab, M_, C_, C_);
}